// round 17
// baseline (speedup 1.0000x reference)
#include <cuda_runtime.h>
#include <cuda_bf16.h>
#include <cstdint>

// Problem shapes (fixed by the dataset)
#define S_LEN 2048
#define BATCH 16
#define DDIM  2048

// Quarter pipeline: stage1 o-range == stage2 d-range.
#define NQ      4
#define QD      512                 // o (and d) per quarter

// Stage-1 per-quarter tiling (R9 proven inner loop)
#define OTILE   256                 // o rows per block (2 per thread)
#define KSPLIT  64
#define KCHUNK  (DDIM / KSPLIT)     // 32 d per block
#define WPAD    33                  // sW bank = (r + d) % 32 -> conflict-free
#define SPAD    20                  // sS row stride (80B, 16B-aligned LDS.128)

#define NS2Q    (64 * 16)           // stage2 blocks per quarter (single wave)

// Scratch (device globals: allocation-free; counters self-reset).
__device__ float g_part[KSPLIT * DDIM * BATCH];   // [kc][o][b], 8 MB
__device__ float g_altered[BATCH * DDIM];         // [b][o], 128 KB
__device__ float g_s2part[NQ * BATCH * S_LEN];    // [q][b][s], 512 KB
__device__ int   g_done;                          // s2 blocks finished
__device__ int   g_fin;                           // final blocks finished

__device__ __forceinline__ void ffma2(uint64_t& d, uint64_t a, uint64_t b) {
    asm("fma.rn.f32x2 %0, %1, %2, %0;" : "+l"(d) : "l"(a), "l"(b));
}

// ---------------------------------------------------------------------------
// Stage1a (per quarter): partial[kc][o][b] for o in [obase0, obase0+512).
// Grid (2, 64) = 128 blocks; R9's proven 2o x 16b FFMA2 tile.
// ---------------------------------------------------------------------------
__global__ void __launch_bounds__(128)
s1_part(const float* __restrict__ state, const float* __restrict__ W,
        int obase0)
{
    __shared__ float sW[OTILE][WPAD];   // 33.8 KB
    __shared__ float sS[KCHUNK][SPAD];  // 2.5 KB

    const int t     = threadIdx.x;
    const int obase = obase0 + blockIdx.x * OTILE;
    const int kc    = blockIdx.y;
    const int d0    = kc * KCHUNK;

    {   // state chunk transposed: sS[d][b]
        const int b  = t >> 3;
        const int c4 = t & 7;
        const float4 v = *(const float4*)(state + b * DDIM + d0 + c4 * 4);
        sS[c4 * 4 + 0][b] = v.x;  sS[c4 * 4 + 1][b] = v.y;
        sS[c4 * 4 + 2][b] = v.z;  sS[c4 * 4 + 3][b] = v.w;
    }
#pragma unroll
    for (int j = 0; j < 16; ++j) {      // W tile 256x32, coalesced
        const int g  = j * 128 + t;
        const int r  = g >> 3;
        const int c4 = g & 7;
        const float4 v = *(const float4*)(W + (long)(obase + r) * DDIM + d0 + c4 * 4);
        sW[r][c4 * 4 + 0] = v.x;  sW[r][c4 * 4 + 1] = v.y;
        sW[r][c4 * 4 + 2] = v.z;  sW[r][c4 * 4 + 3] = v.w;
    }
    __syncthreads();

    uint64_t acc0[8], acc1[8];
#pragma unroll
    for (int i = 0; i < 8; ++i) { acc0[i] = 0ull; acc1[i] = 0ull; }

#pragma unroll 8
    for (int d = 0; d < KCHUNK; ++d) {
        const float w0 = sW[t][d];
        const float w1 = sW[t + 128][d];
        uint64_t wp0, wp1;
        asm("mov.b64 %0, {%1, %1};" : "=l"(wp0) : "r"(__float_as_uint(w0)));
        asm("mov.b64 %0, {%1, %1};" : "=l"(wp1) : "r"(__float_as_uint(w1)));
        const ulonglong2 q0 = *(const ulonglong2*)&sS[d][0];
        const ulonglong2 q1 = *(const ulonglong2*)&sS[d][4];
        const ulonglong2 q2 = *(const ulonglong2*)&sS[d][8];
        const ulonglong2 q3 = *(const ulonglong2*)&sS[d][12];
        ffma2(acc0[0], wp0, q0.x);  ffma2(acc0[1], wp0, q0.y);
        ffma2(acc0[2], wp0, q1.x);  ffma2(acc0[3], wp0, q1.y);
        ffma2(acc0[4], wp0, q2.x);  ffma2(acc0[5], wp0, q2.y);
        ffma2(acc0[6], wp0, q3.x);  ffma2(acc0[7], wp0, q3.y);
        ffma2(acc1[0], wp1, q0.x);  ffma2(acc1[1], wp1, q0.y);
        ffma2(acc1[2], wp1, q1.x);  ffma2(acc1[3], wp1, q1.y);
        ffma2(acc1[4], wp1, q2.x);  ffma2(acc1[5], wp1, q2.y);
        ffma2(acc1[6], wp1, q3.x);  ffma2(acc1[7], wp1, q3.y);
    }

#pragma unroll
    for (int half = 0; half < 2; ++half) {
        const uint64_t* a = half ? acc1 : acc0;
        float res[16];
#pragma unroll
        for (int j = 0; j < 8; ++j)
            asm("mov.b64 {%0, %1}, %2;"
                : "=f"(res[2 * j]), "=f"(res[2 * j + 1]) : "l"(a[j]));
        const int o = obase + t + 128 * half;
        float* dst = g_part + ((long)kc * DDIM + o) * BATCH;
#pragma unroll
        for (int q = 0; q < 4; ++q)
            *(float4*)(dst + q * 4) =
                make_float4(res[q * 4], res[q * 4 + 1], res[q * 4 + 2], res[q * 4 + 3]);
    }
}

// ---------------------------------------------------------------------------
// Stage1b (per quarter): altered[b][o] = bias[o] + sum_kc part[kc][o][b].
// PDL dependent on s1_part(q).
// ---------------------------------------------------------------------------
__global__ void __launch_bounds__(256)
s1_reduce(const float* __restrict__ bias, int obase0)
{
    const int n = blockIdx.x * 256 + threadIdx.x;   // 0..8191
    const int o = obase0 + (n >> 4);
    const int b = n & 15;
    float v = bias[o];
#if __CUDA_ARCH__ >= 900
    cudaGridDependencySynchronize();
#endif
    const long base = (long)o * BATCH + b;
#pragma unroll
    for (int kc = 0; kc < KSPLIT; ++kc)
        v += __ldcg(g_part + (long)kc * DDIM * BATCH + base);
    g_altered[b * DDIM + o] = v;
}

// ---------------------------------------------------------------------------
// Stage2 (per quarter): s2part[q][b][s] = sum_{d in q} altered[b][d]*enc[s][b][d]
// Grid (64,16) = 1024 blocks (single wave, so the early PDL trigger fires
// early). Warp owns 4 s-rows -> 16 independent LDG.128 in flight.
// Triggers completion right after staging alt, so s1_part(q+1) overlaps
// this kernel's 64 MB enc stream.
// ---------------------------------------------------------------------------
__global__ void __launch_bounds__(256)
s2_quarter(const float* __restrict__ enc, int q)
{
    __shared__ float alt[QD];

    const int t    = threadIdx.x;
    const int w    = t >> 5;
    const int lane = t & 31;
    const int b    = blockIdx.y;
    const int s0   = blockIdx.x * 32 + w * 4;
    const int d0   = q * QD;

    const float4* r0 = (const float4*)(enc + ((long)(s0 + 0) * BATCH + b) * DDIM + d0);
    const float4* r1 = (const float4*)(enc + ((long)(s0 + 1) * BATCH + b) * DDIM + d0);
    const float4* r2 = (const float4*)(enc + ((long)(s0 + 2) * BATCH + b) * DDIM + d0);
    const float4* r3 = (const float4*)(enc + ((long)(s0 + 3) * BATCH + b) * DDIM + d0);

#if __CUDA_ARCH__ >= 900
    cudaGridDependencySynchronize();
#endif
    if (t < QD / 4)
        ((float4*)alt)[t] = *(const float4*)(g_altered + b * DDIM + d0 + t * 4);
    __syncthreads();
#if __CUDA_ARCH__ >= 900
    cudaTriggerProgrammaticLaunchCompletion();   // let s1_part(q+1) in early
#endif

    float4 A0 = make_float4(0.f,0.f,0.f,0.f), A1 = A0, A2 = A0, A3 = A0;
#pragma unroll
    for (int i = 0; i < QD / 128; ++i) {         // 4 iters
        const int f4 = i * 32 + lane;
        const float4 a  = ((const float4*)alt)[f4];
        const float4 e0 = __ldcs(r0 + f4);
        const float4 e1 = __ldcs(r1 + f4);
        const float4 e2 = __ldcs(r2 + f4);
        const float4 e3 = __ldcs(r3 + f4);
        A0.x += e0.x*a.x; A0.y += e0.y*a.y; A0.z += e0.z*a.z; A0.w += e0.w*a.w;
        A1.x += e1.x*a.x; A1.y += e1.y*a.y; A1.z += e1.z*a.z; A1.w += e1.w*a.w;
        A2.x += e2.x*a.x; A2.y += e2.y*a.y; A2.z += e2.z*a.z; A2.w += e2.w*a.w;
        A3.x += e3.x*a.x; A3.y += e3.y*a.y; A3.z += e3.z*a.z; A3.w += e3.w*a.w;
    }

    float t0 = (A0.x + A0.y) + (A0.z + A0.w);
    float t1 = (A1.x + A1.y) + (A1.z + A1.w);
    float t2 = (A2.x + A2.y) + (A2.z + A2.w);
    float t3 = (A3.x + A3.y) + (A3.z + A3.w);
#pragma unroll
    for (int off = 16; off > 0; off >>= 1) {
        t0 += __shfl_down_sync(0xFFFFFFFFu, t0, off);
        t1 += __shfl_down_sync(0xFFFFFFFFu, t1, off);
        t2 += __shfl_down_sync(0xFFFFFFFFu, t2, off);
        t3 += __shfl_down_sync(0xFFFFFFFFu, t3, off);
    }
    if (lane == 0) {
        float* dst = g_s2part + (long)q * BATCH * S_LEN + b * S_LEN + s0;
        dst[0] = t0;  dst[1] = t1;  dst[2] = t2;  dst[3] = t3;
    }

    __threadfence();
    __syncthreads();
    if (t == 0) atomicAdd(&g_done, 1);
}

// ---------------------------------------------------------------------------
// Final: out[b][s] = sum_q s2part[q][b][s] (fixed order -> deterministic).
// Counter-guarded against PDL's relaxed completion transitivity; spin is
// deadlock-free (s2 blocks never wait on this kernel). Self-resetting.
// ---------------------------------------------------------------------------
__global__ void __launch_bounds__(256)
final_sum(float* __restrict__ out)
{
    if (threadIdx.x == 0) {
        while (*(volatile int*)&g_done < NQ * NS2Q) __nanosleep(64);
    }
    __syncthreads();
    __threadfence();

    const int idx = blockIdx.x * 256 + threadIdx.x;  // b*S_LEN + s
    float v = __ldcg(&g_s2part[idx]);
#pragma unroll
    for (int q = 1; q < NQ; ++q)
        v += __ldcg(&g_s2part[(long)q * BATCH * S_LEN + idx]);
    out[idx] = v;

    __syncthreads();
    if (threadIdx.x == 0) {
        const int tk = atomicAdd(&g_fin, 1);
        if (tk == (BATCH * S_LEN) / 256 - 1) { g_done = 0; g_fin = 0; }
    }
}

// PDL launch helper (graph-capture legal; proven in R16).
template <typename... Args>
static void launch_pdl(void (*kern)(Args...), dim3 grid, dim3 block,
                       Args... args)
{
    cudaLaunchAttribute attr[1];
    attr[0].id = cudaLaunchAttributeProgrammaticStreamSerialization;
    attr[0].val.programmaticStreamSerializationAllowed = 1;
    cudaLaunchConfig_t cfg = {};
    cfg.gridDim  = grid;
    cfg.blockDim = block;
    cfg.stream   = 0;
    cfg.attrs    = attr;
    cfg.numAttrs = 1;
    cudaLaunchKernelEx(&cfg, kern, args...);
}

extern "C" void kernel_launch(void* const* d_in, const int* in_sizes, int n_in,
                              void* d_out, int out_size)
{
    const float* enc   = (const float*)d_in[0];  // [S, B, D]
    const float* state = (const float*)d_in[1];  // [B, D]
    const float* W     = (const float*)d_in[2];  // [D, D]
    const float* bias  = (const float*)d_in[3];  // [D]
    float* out         = (float*)d_out;          // [B, S]

    for (int q = 0; q < NQ; ++q) {
        if (q == 0)
            s1_part<<<dim3(QD / OTILE, KSPLIT), 128>>>(state, W, 0);
        else
            launch_pdl(s1_part, dim3(QD / OTILE, KSPLIT), dim3(128),
                       state, W, q * QD);
        launch_pdl(s1_reduce, dim3((QD * BATCH) / 256), dim3(256),
                   bias, q * QD);
        launch_pdl(s2_quarter, dim3(64, BATCH), dim3(256), enc, q);
    }
    final_sum<<<(BATCH * S_LEN) / 256, 256>>>(out);
}